// round 10
// baseline (speedup 1.0000x reference)
#include <cuda_runtime.h>

// Patch2Im / fold (col2im) with averaging and crop.
// Input : x_patch [B=4, C=64, K=7, K=7, NH=85, NW=85] fp32 (row-major)
// Output: [B, C, 253, 253] fp32 (padded frame 259x259, crop 3 each side)
//
// v3: cooperative aligned-float4 staging.
// Each block = one (output row h, fused batch*channel bc). Its entire read
// set is ni*7 contiguous ranges of 85 floats (ni = 2 or 3 valid kernel-row
// planes). Phase 1 loads each range as 22 ALIGNED LDG.128 into smem
// (every request 4/4 sectors). Phase 2: 85 compute lanes gather their
// (+1/0/-1)-shifted values from smem, normalize with analytic counts
// (selected reciprocal constants), stage the 253-float row, store coalesced.

namespace {
constexpr int K     = 7;
constexpr int NH    = 85;
constexpr int NW    = 85;
constexpr int PLANE = NH * NW;               // 7225
constexpr int PAD   = 3;
constexpr int HO    = 253;
constexpr int WO    = 253;
constexpr int BC    = 4 * 64;
constexpr long long SLAB  = (long long)K * K * PLANE;   // 354025 (== 1 mod 4)
constexpr long long TOTAL = (long long)BC * SLAB;       // 90630400 floats
constexpr int TPB   = 128;
constexpr int MAXR  = 21;                    // max ranges (3 planes * 7)
constexpr int RW    = 88;                    // smem floats per range (22 f4)
}

__global__ __launch_bounds__(TPB)
void patch2im_kernel(const float* __restrict__ xp, float* __restrict__ out)
{
    __shared__ float sm[MAXR * RW];          // staged input ranges (7.4 KB)
    __shared__ float srow[NW * 3];           // staged output row (255 slots)

    const int h   = blockIdx.x;              // 0..252
    const int bc  = blockIdx.y;              // 0..255
    const int tid = threadIdx.x;             // 0..127
    const int oh  = h + PAD;                 // 3..255

    // Valid kernel-row plane offsets (uniform per block). ni is 2 or 3.
    int offi[3];
    int ni = 0;
    const int ri = oh % 3;
    #pragma unroll
    for (int s = 0; s < 3; ++s) {
        const int i = ri + 3 * s;
        if (i < K) {
            const int d = oh - i;
            if (d >= 0) {
                const int ph = d / 3;
                if (ph < NH) offi[ni++] = i * (K * PLANE) + ph * NW;
            }
        }
    }
    const int nr = 7 * ni;                   // 14 or 21 ranges

    const long long base = (long long)bc * SLAB;

    // ---------------- Phase 1: aligned float4 staging ----------------
    // Range r = (a = r/7, jj = r%7). s_r = offi[a] + jj*PLANE + shift[jj],
    // shift = +1 (jj<3), 0 (jj<6), -1 (jj=6). Elements s_r + t, t in [0,84].
    // Chunk v covers global floats (g & ~3) + 4v .. +3, v = 0..21.
    const int nchunk = nr * 22;
    for (int idx = tid; idx < nchunk; idx += TPB) {
        const int r  = idx / 22;
        const int v  = idx - r * 22;
        const int a  = r / 7;
        const int jj = r - a * 7;
        const int shift = (jj < 3) ? 1 : ((jj < 6) ? 0 : -1);
        const long long g = base + offi[a] + jj * PLANE + shift;
        const long long p = (g & ~3LL) + 4 * v;
        float4 f;
        if (p + 3 < TOTAL) {
            f = __ldcs(reinterpret_cast<const float4*>(xp + p));
        } else {                              // only the tail of the last slab
            f.x = (p + 0 < TOTAL) ? xp[p + 0] : 0.f;
            f.y = (p + 1 < TOTAL) ? xp[p + 1] : 0.f;
            f.z = (p + 2 < TOTAL) ? xp[p + 2] : 0.f;
            f.w = 0.f;
        }
        *reinterpret_cast<float4*>(&sm[r * RW + 4 * v]) = f;
    }
    __syncthreads();

    // ---------------- Phase 2: gather, normalize, stage row ----------------
    if (tid < NW) {
        const int t = tid;                   // column group 0..84
        const bool p012 = (t <= NW - 2);     // +1 shift in range (jj 0..2)
        const bool p6   = (t >= 1);          // -1 shift in range (jj 6)

        float a0 = 0.f, a1 = 0.f, a2 = 0.f;

        #pragma unroll
        for (int a = 0; a < 3; ++a) {
            if (a < ni) {                    // uniform branch
                #pragma unroll
                for (int jj = 0; jj < 7; ++jj) {
                    const int shift = (jj < 3) ? 1 : ((jj < 6) ? 0 : -1);
                    const int s_r = offi[a] + jj * PLANE + shift;
                    // global alignment: SLAB % 4 == 1 -> (bc*SLAB+s_r)&3 = (bc+s_r)&3
                    const int d = (bc + s_r) & 3;
                    const int r = a * 7 + jj;
                    const float v = sm[r * RW + d + t];
                    const bool ok = (jj < 3) ? p012 : ((jj < 6) ? true : p6);
                    if (ok) {
                        const int e = jj % 3;
                        if      (e == 0) a0 += v;
                        else if (e == 1) a1 += v;
                        else             a2 += v;
                    }
                }
            }
        }

        // Analytic normalization (counts are ni * nj, nj from predicates).
        float inv0, inv12;
        if (ni == 3) {
            inv0  = (p012 && p6) ? (1.f / 9.f) : (1.f / 6.f);
            inv12 = p012 ? (1.f / 6.f) : (1.f / 3.f);
        } else {
            inv0  = (p012 && p6) ? (1.f / 6.f) : (1.f / 4.f);
            inv12 = p012 ? (1.f / 4.f) : (1.f / 2.f);
        }
        srow[3 * t + 0] = a0 * inv0;
        srow[3 * t + 1] = a1 * inv12;
        srow[3 * t + 2] = a2 * inv12;
    }
    __syncthreads();

    // ---------------- Phase 3: coalesced row store ----------------
    float* __restrict__ orow = out + ((size_t)bc * HO + h) * WO;
    #pragma unroll
    for (int i = 0; i < 2; ++i) {
        const int w = tid + i * TPB;
        if (w < WO) orow[w] = srow[w];
    }
}

extern "C" void kernel_launch(void* const* d_in, const int* in_sizes, int n_in,
                              void* d_out, int out_size)
{
    (void)in_sizes; (void)n_in; (void)out_size;
    const float* xp = (const float*)d_in[0];
    float* out = (float*)d_out;

    dim3 grid(HO, BC);   // 253 x 256
    dim3 block(TPB);
    patch2im_kernel<<<grid, block>>>(xp, out);
}

// round 11
// speedup vs baseline: 1.1849x; 1.1849x over previous
#include <cuda_runtime.h>

// Patch2Im / fold (col2im) with averaging and crop.
// Input : x_patch [B=4, C=64, K=7, K=7, NH=85, NW=85] fp32 (row-major)
// Output: [B, C, 253, 253] fp32 (padded frame 259x259, crop 3 each side)
//
// v4 = v2 (direct immediate-offset gather) + 2 channels per block.
// Thread t owns output columns ow = 3t+3+e (e=0,1,2). For kernel column j,
// the output with e=j%3 is touched at patch column pw = t+1 - j/3, so all
// 7 loads of a kernel-row plane sit at FIXED immediate offsets from
// (plane_base + t): {+1, P+1, 2P+1, 3P, 4P, 5P, 6P-1}, P = 85*85.
// Processing bc and bc+1 in one block doubles loads-in-flight per thread
// (second slab = same base register + SLAB immediate) and halves per-block
// setup/store overhead. Normalization counts are analytic constants.

namespace {
constexpr int K     = 7;
constexpr int NH    = 85;
constexpr int NW    = 85;
constexpr int PLANE = NH * NW;          // 7225
constexpr int SLAB  = K * K * PLANE;    // 354025 floats (1.35 MB: fits imm)
constexpr int PAD   = 3;
constexpr int HO    = 253;
constexpr int WO    = 253;
constexpr int BC    = 4 * 64;
constexpr int TPB   = 96;
constexpr int TGRP  = 85;
}

// One kernel-row plane for one channel: 7 loads at constant immediate
// offsets, boundary groups predicated (@P LDG, no branches).
__device__ __forceinline__ void accum_plane(const float* __restrict__ q,
                                            bool p012, bool p6,
                                            float& a0, float& a1, float& a2)
{
    if (p012) {                               // pw = t+1 (t <= 83)
        a0 += __ldcs(q + 1);                  // j=0
        a1 += __ldcs(q + PLANE + 1);          // j=1
        a2 += __ldcs(q + 2 * PLANE + 1);      // j=2
    }
    a0 += __ldcs(q + 3 * PLANE);              // j=3 (pw = t)
    a1 += __ldcs(q + 4 * PLANE);              // j=4
    a2 += __ldcs(q + 5 * PLANE);              // j=5
    if (p6)                                   // pw = t-1 (t >= 1)
        a0 += __ldcs(q + 6 * PLANE - 1);      // j=6
}

__global__ __launch_bounds__(TPB)
void patch2im_kernel(const float* __restrict__ xp, float* __restrict__ out)
{
    const int h   = blockIdx.x;          // output row 0..252
    const int bc0 = blockIdx.y * 2;      // fused batch*channel pair
    const int t   = threadIdx.x;         // 0..95

    __shared__ float sm[2][TGRP * 3];

    const int oh = h + PAD;              // padded row coord 3..255

    // Valid kernel-row plane offsets (uniform per block). ni is 2 or 3.
    int offi[3];
    int ni = 0;
    const int ri = oh % 3;
    #pragma unroll
    for (int s = 0; s < 3; ++s) {
        const int i = ri + 3 * s;
        if (i < K) {
            const int d = oh - i;
            if (d >= 0) {
                const int ph = d / 3;
                if (ph < NH) offi[ni++] = i * (K * PLANE) + ph * NW;
            }
        }
    }

    if (t < TGRP) {
        const float* __restrict__ base =
            xp + (size_t)bc0 * SLAB + t;

        const bool p012 = (t <= NW - 2);   // t <= 83
        const bool p6   = (t >= 1);

        float x0 = 0.f, x1 = 0.f, x2 = 0.f;   // channel bc0
        float y0 = 0.f, y1 = 0.f, y2 = 0.f;   // channel bc0+1

        if (ni == 3) {                     // uniform branch (whole block)
            accum_plane(base + offi[0],        p012, p6, x0, x1, x2);
            accum_plane(base + offi[0] + SLAB, p012, p6, y0, y1, y2);
            accum_plane(base + offi[1],        p012, p6, x0, x1, x2);
            accum_plane(base + offi[1] + SLAB, p012, p6, y0, y1, y2);
            accum_plane(base + offi[2],        p012, p6, x0, x1, x2);
            accum_plane(base + offi[2] + SLAB, p012, p6, y0, y1, y2);
            const float inv0  = (p012 && p6) ? (1.f / 9.f) : (1.f / 6.f);
            const float inv12 = p012 ? (1.f / 6.f) : (1.f / 3.f);
            x0 *= inv0;  x1 *= inv12;  x2 *= inv12;
            y0 *= inv0;  y1 *= inv12;  y2 *= inv12;
        } else {
            accum_plane(base + offi[0],        p012, p6, x0, x1, x2);
            accum_plane(base + offi[0] + SLAB, p012, p6, y0, y1, y2);
            accum_plane(base + offi[1],        p012, p6, x0, x1, x2);
            accum_plane(base + offi[1] + SLAB, p012, p6, y0, y1, y2);
            const float inv0  = (p012 && p6) ? (1.f / 6.f) : (1.f / 4.f);
            const float inv12 = p012 ? (1.f / 4.f) : (1.f / 2.f);
            x0 *= inv0;  x1 *= inv12;  x2 *= inv12;
            y0 *= inv0;  y1 *= inv12;  y2 *= inv12;
        }

        // Stage (stride-3 STS: bank-conflict-free, gcd(3,32)=1).
        sm[0][3 * t + 0] = x0;
        sm[0][3 * t + 1] = x1;
        sm[0][3 * t + 2] = x2;
        sm[1][3 * t + 0] = y0;
        sm[1][3 * t + 1] = y1;
        sm[1][3 * t + 2] = y2;
    }

    __syncthreads();

    // Coalesced row stores: 2 x 253 floats with 96 threads.
    float* __restrict__ orow0 = out + ((size_t)bc0 * HO + h) * WO;
    float* __restrict__ orow1 = orow0 + (size_t)HO * WO;
    #pragma unroll
    for (int idx = 0; idx < 3; ++idx) {
        const int w = t + idx * TPB;
        if (w < WO) {
            orow0[w] = sm[0][w];
            orow1[w] = sm[1][w];
        }
    }
}

extern "C" void kernel_launch(void* const* d_in, const int* in_sizes, int n_in,
                              void* d_out, int out_size)
{
    (void)in_sizes; (void)n_in; (void)out_size;
    const float* xp = (const float*)d_in[0];
    float* out = (float*)d_out;

    dim3 grid(HO, BC / 2);   // 253 x 128
    dim3 block(TPB);
    patch2im_kernel<<<grid, block>>>(xp, out);
}

// round 12
// speedup vs baseline: 1.2837x; 1.0833x over previous
#include <cuda_runtime.h>

// Patch2Im / fold (col2im) with averaging and crop.
// Input : x_patch [B=4, C=64, K=7, K=7, NH=85, NW=85] fp32 (row-major)
// Output: [B, C, 253, 253] fp32 (padded frame 259x259, crop 3 each side)
//
// v5 = v2 (direct immediate-offset gather, 21 loads/thread) + 3 rows/block.
// Lane (g, u): g = tid/85 selects output row h0+g, u = tid%85 is the
// column group owning ow = 3u+3+e (e=0,1,2). For kernel column j the
// output with e=j%3 reads patch column pw = u+1-j/3, so all 7 loads of a
// kernel-row plane sit at FIXED immediate offsets from (plane_base + u):
//   {+1, P+1, 2P+1, 3P, 4P, 5P, 6P-1},  P = 85*85.
// 255/256 lanes active, 32/32 resident warps/SM, and the 3 rows of one
// (bc) are a contiguous 759-float output span -> one coalesced store loop.
// Normalization counts are analytic (ni * nj from predicates).

namespace {
constexpr int K     = 7;
constexpr int NH    = 85;
constexpr int NW    = 85;
constexpr int PLANE = NH * NW;          // 7225
constexpr int SLAB  = K * K * PLANE;    // 354025 floats per (b,c) slab
constexpr int PAD   = 3;
constexpr int HO    = 253;
constexpr int WO    = 253;
constexpr int BC    = 4 * 64;
constexpr int TPB   = 256;
constexpr int RPB   = 3;                // rows per block
constexpr int NGRP  = (HO + RPB - 1) / RPB;   // 85 row groups
}

__global__ __launch_bounds__(TPB)
void patch2im_kernel(const float* __restrict__ xp, float* __restrict__ out)
{
    __shared__ float srow[RPB * WO];     // 759 staged output floats

    const int tid = threadIdx.x;
    const int bc  = blockIdx.y;
    const int h0  = blockIdx.x * RPB;

    const int g = tid / NW;              // 0..3 (3 = spare lane)
    const int u = tid - g * NW;          // 0..84

    const int h = h0 + g;
    const bool valid = (g < RPB) && (h < HO);

    if (valid) {
        const int oh = h + PAD;          // 3..255

        // Valid kernel-row plane offsets for this lane's row. ni is 2 or 3.
        int offi[3];
        int ni = 0;
        const int ri = oh % 3;
        #pragma unroll
        for (int s = 0; s < 3; ++s) {
            const int i = ri + 3 * s;
            if (i < K) {
                const int d = oh - i;
                if (d >= 0) {
                    const int ph = d / 3;
                    if (ph < NH) offi[ni++] = i * (K * PLANE) + ph * NW;
                }
            }
        }
        if (ni == 2) offi[2] = offi[1];  // safe address; loads predicated off

        const bool p2   = (ni == 3);
        const bool p012 = (u <= NW - 2); // pw = u+1 valid
        const bool p6   = (u >= 1);      // pw = u-1 valid

        const float* __restrict__ base = xp + (size_t)bc * SLAB + u;

        float a0 = 0.f, a1 = 0.f, a2 = 0.f;
        #pragma unroll
        for (int a = 0; a < 3; ++a) {
            const float* __restrict__ q = base + offi[a];
            const bool pa = (a < 2) || p2;
            if (pa && p012) {
                a0 += __ldcs(q + 1);                 // j=0
                a1 += __ldcs(q + PLANE + 1);         // j=1
                a2 += __ldcs(q + 2 * PLANE + 1);     // j=2
            }
            if (pa) {
                a0 += __ldcs(q + 3 * PLANE);         // j=3
                a1 += __ldcs(q + 4 * PLANE);         // j=4
                a2 += __ldcs(q + 5 * PLANE);         // j=5
            }
            if (pa && p6)
                a0 += __ldcs(q + 6 * PLANE - 1);     // j=6
        }

        // Analytic normalization: count = ni * nj.
        const int nj0  = 1 + (int)p012 + (int)p6;    // j in {0,3,6}
        const int nj12 = 1 + (int)p012;              // j in {1,4} / {2,5}
        const float inv0  = __fdividef(1.f, (float)(ni * nj0));
        const float inv12 = __fdividef(1.f, (float)(ni * nj12));
        a0 *= inv0;  a1 *= inv12;  a2 *= inv12;

        // Stage into the flat 3-row buffer (stride-3 STS, bank-clean).
        const int c0 = 3 * u;            // 0..252
        float* __restrict__ s = srow + g * WO;
        s[c0] = a0;                      // c0 <= 252 always valid
        if (c0 + 1 < WO) s[c0 + 1] = a1;
        if (c0 + 2 < WO) s[c0 + 2] = a2;
    }

    __syncthreads();

    // Rows h0..h0+nrows-1 of channel bc are one contiguous output span.
    const int nrows = (HO - h0 < RPB) ? (HO - h0) : RPB;
    const int total = nrows * WO;        // 759 (or 253 for the last group)
    float* __restrict__ o = out + ((size_t)bc * HO + h0) * WO;
    for (int w = tid; w < total; w += TPB)
        o[w] = srow[w];
}

extern "C" void kernel_launch(void* const* d_in, const int* in_sizes, int n_in,
                              void* d_out, int out_size)
{
    (void)in_sizes; (void)n_in; (void)out_size;
    const float* xp = (const float*)d_in[0];
    float* out = (float*)d_out;

    dim3 grid(NGRP, BC);   // 85 x 256
    dim3 block(TPB);
    patch2im_kernel<<<grid, block>>>(xp, out);
}